// round 11
// baseline (speedup 1.0000x reference)
#include <cuda_runtime.h>

// MFNet two-layer MFConv — CSR gather + degree-sorted node permutation.
// fused1 profile showed L1-wavefront-bound (73.5%), dominated by per-node
// weight re-reads whenever a warp's nodes span degree buckets. Fix:
//  - counting-sort nodes by clamped degree -> warps are bucket-uniform,
//  - GRP=8 nodes/warp so each weight load feeds 8 fma.rn.f32x2.
// 6 launches: hist, alloc(+bucket count+pack), bbase, place(+perm), fused1,
// fused2. Replay-safe: g_deg restored by k_place, g_bcnt by k_bbase,
// g_total by k_fused2; everything else fully rewritten each run.

#define NMAX 100352
#define EMAX 1664000
#define FIN  128
#define FH   32
#define FO   64
#define DMAX 10
#define TPB  256
#define TPB1 128            // fused1 block (4 warps -> 32KB static smem)
#define GRP  8
#define NW1  (11 * FIN * FH)   // 45056
#define NW2  (11 * FH * FO)    // 22528

typedef unsigned long long u64;

// scratch (static __device__ — no allocations allowed)
__device__ int g_deg[NMAX];      // INVARIANT: zero at entry (restored: k_place)
__device__ int g_total;          // INVARIANT: zero at entry (restored: k_fused2)
__device__ int g_bcnt[16];       // INVARIANT: zero at entry (restored: k_bbase)
__device__ int g_bcur[16];
__device__ int g_perm[NMAX];
__device__ int g_rowbeg[NMAX];
__device__ int g_rowend[NMAX];
__device__ int g_cursor[NMAX];
__device__ int g_csr[EMAX];
__device__ __align__(16) float g_h[NMAX * FH];     // 12.8 MB
__device__ __align__(16) u64 g_Wp1[NW1];           // (W1,Wr1) interleaved
__device__ __align__(16) u64 g_Wp2[NW2];           // (W2,Wr2) interleaved

__device__ __forceinline__ u64 pack2(float lo, float hi) {
    u64 r; asm("mov.b64 %0, {%1, %2};" : "=l"(r) : "f"(lo), "f"(hi)); return r;
}
__device__ __forceinline__ void unpack2(u64 v, float& lo, float& hi) {
    asm("mov.b64 {%0, %1}, %2;" : "=f"(lo), "=f"(hi) : "l"(v));
}
__device__ __forceinline__ void fma2(u64& d, u64 a, u64 b) {
    asm("fma.rn.f32x2 %0, %1, %2, %0;" : "+l"(d) : "l"(a), "l"(b));
}

// ------------------------------------------- [0] degree histogram (deg==0 in)
__global__ void k_hist(const int* __restrict__ ei, int E, int N) {
    int e = blockIdx.x * blockDim.x + threadIdx.x;
    if (e >= E) return;
    int d = __ldg(ei + E + e);
    if ((unsigned)d < (unsigned)N) atomicAdd(g_deg + d, 1);
}

// -------- [1] CSR slice alloc (warp-aggregated) + bucket count + weight pack
__global__ void k_alloc(const float* __restrict__ W1, const float* __restrict__ Wr1,
                        const float* __restrict__ W2, const float* __restrict__ Wr2,
                        int N) {
    int i = blockIdx.x * blockDim.x + threadIdx.x;
    if (i < NW1) g_Wp1[i] = pack2(__ldg(W1 + i), __ldg(Wr1 + i));
    if (i < NW2) g_Wp2[i] = pack2(__ldg(W2 + i), __ldg(Wr2 + i));

    int lane = threadIdx.x & 31;
    int d = (i < N) ? g_deg[i] : 0;
    if (i < N) atomicAdd(g_bcnt + min(d, DMAX), 1);
    int incl = d;
#pragma unroll
    for (int off = 1; off < 32; off <<= 1) {
        int v = __shfl_up_sync(0xffffffffu, incl, off);
        if (lane >= off) incl += v;
    }
    int wtot = __shfl_sync(0xffffffffu, incl, 31);
    int base = 0;
    if (lane == 31) base = atomicAdd(&g_total, wtot);
    base = __shfl_sync(0xffffffffu, base, 31);
    int beg = base + incl - d;
    if (i < N) { g_rowbeg[i] = beg; g_rowend[i] = beg + d; g_cursor[i] = beg; }
}

// -------------- [2] bucket bases (1 warp); restores g_bcnt=0 entry invariant
__global__ void k_bbase() {
    int lane = threadIdx.x;
    int c = (lane <= DMAX) ? g_bcnt[lane] : 0;
    int incl = c;
#pragma unroll
    for (int off = 1; off < 32; off <<= 1) {
        int v = __shfl_up_sync(0xffffffffu, incl, off);
        if (lane >= off) incl += v;
    }
    if (lane <= DMAX) { g_bcur[lane] = incl - c; g_bcnt[lane] = 0; }
}

// ---------- [3] CSR placement + node perm; restores g_deg=0 entry invariant
__global__ void k_place(const int* __restrict__ ei, int E, int N) {
    int e = blockIdx.x * blockDim.x + threadIdx.x;
    if (e < N) {
        g_deg[e] = 0;                        // consumed by k_alloc; restore
        int b = min(g_rowend[e] - g_rowbeg[e], DMAX);
        int pos = atomicAdd(g_bcur + b, 1);
        if (pos < N) g_perm[pos] = e;
    }
    if (e >= E) return;
    int s = __ldg(ei + e);
    int d = __ldg(ei + E + e);
    if ((unsigned)s >= (unsigned)N || (unsigned)d >= (unsigned)N) return;
    int pos = atomicAdd(g_cursor + d, 1);
    if (pos < EMAX) g_csr[pos] = s;
}

// ------------------------ [4] layer 1: fused gather + transform (GRP=8 perm)
// Warp handles 8 bucket-uniform nodes. Gather: lane owns features [4L,4L+4),
// chunk-of-4 index prefetch (MLP 4). (sum,x) packed in smem; matvec: one
// LDG.64 weight pair feeds 8 FFMA2 (weight L1 traffic 4KB/node).
__global__ __launch_bounds__(TPB1) void k_fused1(const float* __restrict__ x,
                                                 const float* __restrict__ b1, int N) {
    __shared__ u64 sh[TPB1 / 32][GRP * FIN];   // 4 warps x 8KB = 32KB
    int gw = (blockIdx.x * blockDim.x + threadIdx.x) >> 5;
    int lane = threadIdx.x & 31;
    u64* hx = sh[threadIdx.x >> 5];
    int base = gw * GRP;
    if (base >= N) return;

    int pm[GRP], dg[GRP];
#pragma unroll
    for (int g = 0; g < GRP; g++) {
        int idx = base + g;
        int n = (idx < N) ? g_perm[idx] : -1;
        pm[g] = n;
        float a0 = 0.f, a1 = 0.f, a2 = 0.f, a3 = 0.f;
        float4 xr = make_float4(0.f, 0.f, 0.f, 0.f);
        int d = 0;
        if (n >= 0) {
            int beg = g_rowbeg[n], end = g_rowend[n];
            d = min(end - beg, DMAX);
            int j = beg;
            for (; j + 4 <= end; j += 4) {
                int s0 = __ldg(g_csr + j + 0);
                int s1 = __ldg(g_csr + j + 1);
                int s2 = __ldg(g_csr + j + 2);
                int s3 = __ldg(g_csr + j + 3);
                float4 v0 = *reinterpret_cast<const float4*>(x + (size_t)s0 * FIN + lane * 4);
                float4 v1 = *reinterpret_cast<const float4*>(x + (size_t)s1 * FIN + lane * 4);
                float4 v2 = *reinterpret_cast<const float4*>(x + (size_t)s2 * FIN + lane * 4);
                float4 v3 = *reinterpret_cast<const float4*>(x + (size_t)s3 * FIN + lane * 4);
                a0 += v0.x + v1.x + v2.x + v3.x;
                a1 += v0.y + v1.y + v2.y + v3.y;
                a2 += v0.z + v1.z + v2.z + v3.z;
                a3 += v0.w + v1.w + v2.w + v3.w;
            }
            for (; j < end; j++) {
                int s = __ldg(g_csr + j);
                float4 v = *reinterpret_cast<const float4*>(x + (size_t)s * FIN + lane * 4);
                a0 += v.x; a1 += v.y; a2 += v.z; a3 += v.w;
            }
            xr = *reinterpret_cast<const float4*>(x + (size_t)n * FIN + lane * 4);
        }
        dg[g] = d;
        hx[g * FIN + 4 * lane + 0] = pack2(a0, xr.x);
        hx[g * FIN + 4 * lane + 1] = pack2(a1, xr.y);
        hx[g * FIN + 4 * lane + 2] = pack2(a2, xr.z);
        hx[g * FIN + 4 * lane + 3] = pack2(a3, xr.w);
    }
    __syncwarp();

    u64 acc[GRP];
#pragma unroll
    for (int g = 0; g < GRP; g++)
        acc[g] = pack2(__ldg(b1 + dg[g] * FH + lane), 0.f);

    bool uni = (pm[GRP - 1] >= 0);
#pragma unroll
    for (int g = 1; g < GRP; g++) uni = uni && (dg[g] == dg[0]);

    if (uni) {
        const u64* Wp = g_Wp1 + dg[0] * FIN * FH;
#pragma unroll 8
        for (int f = 0; f < FIN; f++) {
            u64 wv = __ldg(Wp + f * FH + lane);
#pragma unroll
            for (int g = 0; g < GRP; g++) fma2(acc[g], hx[g * FIN + f], wv);
        }
    } else {
#pragma unroll
        for (int g = 0; g < GRP; g++) {
            if (pm[g] < 0) continue;
            const u64* Wp = g_Wp1 + dg[g] * FIN * FH;
#pragma unroll 8
            for (int f = 0; f < FIN; f++)
                fma2(acc[g], hx[g * FIN + f], __ldg(Wp + f * FH + lane));
        }
    }
#pragma unroll
    for (int g = 0; g < GRP; g++) {
        if (pm[g] >= 0) {
            float lo, hi; unpack2(acc[g], lo, hi);
            g_h[(size_t)pm[g] * FH + lane] = fmaxf(lo + hi, 0.f);
        }
    }
}

// ------ [5] layer 2: fused gather + transform (GRP=8, two output halves);
//            restores g_total=0 entry invariant
__global__ __launch_bounds__(TPB) void k_fused2(const float* __restrict__ b2,
                                                float* __restrict__ out, int N) {
    if (blockIdx.x == 0 && threadIdx.x == 0) g_total = 0;
    __shared__ u64 sh[TPB / 32][GRP * FH];   // 8 warps x 2KB = 16KB
    int gw = (blockIdx.x * blockDim.x + threadIdx.x) >> 5;
    int lane = threadIdx.x & 31;
    u64* hh = sh[threadIdx.x >> 5];
    int base = gw * GRP;
    if (base >= N) return;

    int pm[GRP], dg[GRP];
#pragma unroll
    for (int g = 0; g < GRP; g++) {
        int idx = base + g;
        int n = (idx < N) ? g_perm[idx] : -1;
        pm[g] = n;
        float hs = 0.f, hn = 0.f;
        int d = 0;
        if (n >= 0) {
            int beg = g_rowbeg[n], end = g_rowend[n];
            d = min(end - beg, DMAX);
            int j = beg;
            for (; j + 4 <= end; j += 4) {
                int s0 = __ldg(g_csr + j + 0);
                int s1 = __ldg(g_csr + j + 1);
                int s2 = __ldg(g_csr + j + 2);
                int s3 = __ldg(g_csr + j + 3);
                hs += g_h[(size_t)s0 * FH + lane] + g_h[(size_t)s1 * FH + lane]
                    + g_h[(size_t)s2 * FH + lane] + g_h[(size_t)s3 * FH + lane];
            }
            for (; j < end; j++) {
                int s = __ldg(g_csr + j);
                hs += g_h[(size_t)s * FH + lane];
            }
            hn = g_h[(size_t)n * FH + lane];
        }
        dg[g] = d;
        hh[g * FH + lane] = pack2(hs, hn);
    }
    __syncwarp();

    bool uni = (pm[GRP - 1] >= 0);
#pragma unroll
    for (int g = 1; g < GRP; g++) uni = uni && (dg[g] == dg[0]);

    // two sequential output-half passes keep accumulators at 8 u64 each
#pragma unroll
    for (int half = 0; half < 2; half++) {
        int o = half * 32 + lane;
        u64 acc[GRP];
#pragma unroll
        for (int g = 0; g < GRP; g++)
            acc[g] = pack2(__ldg(b2 + dg[g] * FO + o), 0.f);

        if (uni) {
            const u64* Wp = g_Wp2 + dg[0] * FH * FO;
#pragma unroll 8
            for (int j = 0; j < FH; j++) {
                u64 wv = __ldg(Wp + j * FO + o);
#pragma unroll
                for (int g = 0; g < GRP; g++) fma2(acc[g], hh[g * FH + j], wv);
            }
        } else {
#pragma unroll
            for (int g = 0; g < GRP; g++) {
                if (pm[g] < 0) continue;
                const u64* Wp = g_Wp2 + dg[g] * FH * FO;
#pragma unroll 8
                for (int j = 0; j < FH; j++)
                    fma2(acc[g], hh[g * FH + j], __ldg(Wp + j * FO + o));
            }
        }
#pragma unroll
        for (int g = 0; g < GRP; g++) {
            if (pm[g] >= 0) {
                float lo, hi; unpack2(acc[g], lo, hi);
                out[(size_t)pm[g] * FO + o] = lo + hi;
            }
        }
    }
}

// ============================================================================
extern "C" void kernel_launch(void* const* d_in, const int* in_sizes, int n_in,
                              void* d_out, int out_size) {
    const float* x   = (const float*)d_in[0];
    const int*   ei  = (const int*)d_in[1];     // int32 (JAX x64 disabled)
    const float* W1  = (const float*)d_in[2];
    const float* b1  = (const float*)d_in[3];
    const float* Wr1 = (const float*)d_in[4];
    const float* W2  = (const float*)d_in[5];
    const float* b2  = (const float*)d_in[6];
    const float* Wr2 = (const float*)d_in[7];
    float* out = (float*)d_out;

    int N = in_sizes[0] / FIN;
    int E = in_sizes[1] / 2;
    if (N > NMAX) N = NMAX;
    if (E > EMAX) E = EMAX;

    int nb    = (N + TPB - 1) / TPB;           // covers NW1=45056 too
    int egrid = (E + TPB - 1) / TPB;
    int nwarps = (N + GRP - 1) / GRP;
    int f1grid = (nwarps * 32 + TPB1 - 1) / TPB1;
    int f2grid = (nwarps * 32 + TPB - 1) / TPB;

    k_hist  <<<egrid, TPB>>>(ei, E, N);
    k_alloc <<<nb,    TPB>>>(W1, Wr1, W2, Wr2, N);
    k_bbase <<<1, 32>>>();
    k_place <<<egrid, TPB>>>(ei, E, N);
    k_fused1<<<f1grid, TPB1>>>(x, b1, N);
    k_fused2<<<f2grid, TPB>>>(b2, out, N);
}

// round 12
// speedup vs baseline: 1.3446x; 1.3446x over previous
#include <cuda_runtime.h>

// MFNet two-layer MFConv — R10 pipeline (5 launches, no global sort) with a
// majority-bucket weight-sharing matvec (GRP=8):
//  ~96% of nodes have clamped deg==10, so each warp shares ONE bucket-10
//  weight stream across its deg==10 nodes (predicated), and only the rare
//  exceptions (~4%) take a serial per-node weight loop. No contended atomics
//  (R11's 100K-atomics-on-11-addresses regression is reverted).
// Replay-safe: g_deg restored by k_place, g_total by k_fused2; all other
// state fully rewritten each run.

#define NMAX 100352
#define EMAX 1664000
#define FIN  128
#define FH   32
#define FO   64
#define DMAX 10
#define TPB  256
#define TPB1 128            // fused1 block (4 warps -> 32KB static smem)
#define GRP  8
#define NW1  (11 * FIN * FH)   // 45056
#define NW2  (11 * FH * FO)    // 22528

typedef unsigned long long u64;

// scratch (static __device__ — no allocations allowed)
__device__ int g_deg[NMAX];      // INVARIANT: zero at entry (restored: k_place)
__device__ int g_total;          // INVARIANT: zero at entry (restored: k_fused2)
__device__ int g_rowbeg[NMAX];
__device__ int g_rowend[NMAX];
__device__ int g_cursor[NMAX];
__device__ int g_csr[EMAX];
__device__ __align__(16) float g_h[NMAX * FH];     // 12.8 MB
__device__ __align__(16) u64 g_Wp1[NW1];           // (W1,Wr1) interleaved
__device__ __align__(16) u64 g_Wp2[NW2];           // (W2,Wr2) interleaved

__device__ __forceinline__ u64 pack2(float lo, float hi) {
    u64 r; asm("mov.b64 %0, {%1, %2};" : "=l"(r) : "f"(lo), "f"(hi)); return r;
}
__device__ __forceinline__ void unpack2(u64 v, float& lo, float& hi) {
    asm("mov.b64 {%0, %1}, %2;" : "=f"(lo), "=f"(hi) : "l"(v));
}
__device__ __forceinline__ void fma2(u64& d, u64 a, u64 b) {
    asm("fma.rn.f32x2 %0, %1, %2, %0;" : "+l"(d) : "l"(a), "l"(b));
}

// ------------------------------------------- [0] degree histogram (deg==0 in)
__global__ void k_hist(const int* __restrict__ ei, int E, int N) {
    int e = blockIdx.x * blockDim.x + threadIdx.x;
    if (e >= E) return;
    int d = __ldg(ei + E + e);
    if ((unsigned)d < (unsigned)N) atomicAdd(g_deg + d, 1);
}

// ---------------- [1] slice allocation (warp-aggregated atomic) + weight pack
__global__ void k_alloc(const float* __restrict__ W1, const float* __restrict__ Wr1,
                        const float* __restrict__ W2, const float* __restrict__ Wr2,
                        int N) {
    int i = blockIdx.x * blockDim.x + threadIdx.x;
    if (i < NW1) g_Wp1[i] = pack2(__ldg(W1 + i), __ldg(Wr1 + i));
    if (i < NW2) g_Wp2[i] = pack2(__ldg(W2 + i), __ldg(Wr2 + i));

    int lane = threadIdx.x & 31;
    int d = (i < N) ? g_deg[i] : 0;
    int incl = d;
#pragma unroll
    for (int off = 1; off < 32; off <<= 1) {
        int v = __shfl_up_sync(0xffffffffu, incl, off);
        if (lane >= off) incl += v;
    }
    int wtot = __shfl_sync(0xffffffffu, incl, 31);
    int base = 0;
    if (lane == 31) base = atomicAdd(&g_total, wtot);
    base = __shfl_sync(0xffffffffu, base, 31);
    int beg = base + incl - d;
    if (i < N) { g_rowbeg[i] = beg; g_rowend[i] = beg + d; g_cursor[i] = beg; }
}

// ---------------------- [2] CSR placement; restores g_deg=0 entry invariant
__global__ void k_place(const int* __restrict__ ei, int E, int N) {
    int e = blockIdx.x * blockDim.x + threadIdx.x;
    if (e < N) g_deg[e] = 0;                 // deg consumed by k_alloc; restore
    if (e >= E) return;
    int s = __ldg(ei + e);
    int d = __ldg(ei + E + e);
    if ((unsigned)s >= (unsigned)N || (unsigned)d >= (unsigned)N) return;
    int pos = atomicAdd(g_cursor + d, 1);
    if (pos < EMAX) g_csr[pos] = s;
}

// -------------------- [3] layer 1: fused gather + transform  (PROFILED SLOT)
// Warp handles 8 nodes. Gather: lane owns features [4L,4L+4); chunk-of-4 index
// prefetch (MLP 4). (sum,x) packed in smem. Matvec: one bucket-10 weight
// stream shared (predicated) across all deg==10 nodes; serial loops only for
// the rare exceptions.
__global__ __launch_bounds__(TPB1) void k_fused1(const float* __restrict__ x,
                                                 const float* __restrict__ b1, int N) {
    __shared__ u64 sh[TPB1 / 32][GRP * FIN];   // 4 warps x 8KB = 32KB
    int gw = (blockIdx.x * blockDim.x + threadIdx.x) >> 5;
    int lane = threadIdx.x & 31;
    u64* hx = sh[threadIdx.x >> 5];
    int base = gw * GRP;
    if (base >= N) return;

    int dg[GRP];                   // clamped degree; -1 for out-of-range slot
#pragma unroll
    for (int g = 0; g < GRP; g++) {
        int n = base + g;
        float a0 = 0.f, a1 = 0.f, a2 = 0.f, a3 = 0.f;
        float4 xr = make_float4(0.f, 0.f, 0.f, 0.f);
        int d = -1;
        if (n < N) {
            int beg = g_rowbeg[n], end = g_rowend[n];
            d = min(end - beg, DMAX);
            int j = beg;
            for (; j + 4 <= end; j += 4) {
                int s0 = __ldg(g_csr + j + 0);
                int s1 = __ldg(g_csr + j + 1);
                int s2 = __ldg(g_csr + j + 2);
                int s3 = __ldg(g_csr + j + 3);
                float4 v0 = *reinterpret_cast<const float4*>(x + (size_t)s0 * FIN + lane * 4);
                float4 v1 = *reinterpret_cast<const float4*>(x + (size_t)s1 * FIN + lane * 4);
                float4 v2 = *reinterpret_cast<const float4*>(x + (size_t)s2 * FIN + lane * 4);
                float4 v3 = *reinterpret_cast<const float4*>(x + (size_t)s3 * FIN + lane * 4);
                a0 += v0.x + v1.x + v2.x + v3.x;
                a1 += v0.y + v1.y + v2.y + v3.y;
                a2 += v0.z + v1.z + v2.z + v3.z;
                a3 += v0.w + v1.w + v2.w + v3.w;
            }
            for (; j < end; j++) {
                int s = __ldg(g_csr + j);
                float4 v = *reinterpret_cast<const float4*>(x + (size_t)s * FIN + lane * 4);
                a0 += v.x; a1 += v.y; a2 += v.z; a3 += v.w;
            }
            xr = *reinterpret_cast<const float4*>(x + (size_t)n * FIN + lane * 4);
        }
        dg[g] = d;
        hx[g * FIN + 4 * lane + 0] = pack2(a0, xr.x);
        hx[g * FIN + 4 * lane + 1] = pack2(a1, xr.y);
        hx[g * FIN + 4 * lane + 2] = pack2(a2, xr.z);
        hx[g * FIN + 4 * lane + 3] = pack2(a3, xr.w);
    }
    __syncwarp();

    u64 acc[GRP];
#pragma unroll
    for (int g = 0; g < GRP; g++)
        acc[g] = pack2((dg[g] >= 0) ? __ldg(b1 + dg[g] * FH + lane) : 0.f, 0.f);

    bool all10 = true;
#pragma unroll
    for (int g = 0; g < GRP; g++) all10 = all10 && (dg[g] == DMAX);

    const u64* W10 = g_Wp1 + DMAX * FIN * FH;
    if (all10) {                           // ~70% of warps: clean shared pass
#pragma unroll 8
        for (int f = 0; f < FIN; f++) {
            u64 wv = __ldg(W10 + f * FH + lane);
#pragma unroll
            for (int g = 0; g < GRP; g++) fma2(acc[g], hx[g * FIN + f], wv);
        }
    } else {                               // predicated shared pass + exceptions
#pragma unroll 8
        for (int f = 0; f < FIN; f++) {
            u64 wv = __ldg(W10 + f * FH + lane);
#pragma unroll
            for (int g = 0; g < GRP; g++)
                if (dg[g] == DMAX) fma2(acc[g], hx[g * FIN + f], wv);
        }
#pragma unroll
        for (int g = 0; g < GRP; g++) {
            if (dg[g] < 0 || dg[g] == DMAX) continue;
            const u64* Wp = g_Wp1 + dg[g] * FIN * FH;
#pragma unroll 8
            for (int f = 0; f < FIN; f++)
                fma2(acc[g], hx[g * FIN + f], __ldg(Wp + f * FH + lane));
        }
    }
#pragma unroll
    for (int g = 0; g < GRP; g++) {
        int n = base + g;
        if (dg[g] >= 0) {
            float lo, hi; unpack2(acc[g], lo, hi);
            g_h[(size_t)n * FH + lane] = fmaxf(lo + hi, 0.f);
        }
    }
}

// ------------- [4] layer 2: fused gather + transform; restores g_total=0
__global__ __launch_bounds__(TPB) void k_fused2(const float* __restrict__ b2,
                                                float* __restrict__ out, int N) {
    if (blockIdx.x == 0 && threadIdx.x == 0) g_total = 0;  // restore invariant
    __shared__ u64 sh[TPB / 32][GRP * FH];   // 8 warps x 2KB = 16KB
    int gw = (blockIdx.x * blockDim.x + threadIdx.x) >> 5;
    int lane = threadIdx.x & 31;
    u64* hh = sh[threadIdx.x >> 5];
    int base = gw * GRP;
    if (base >= N) return;

    int dg[GRP];
#pragma unroll
    for (int g = 0; g < GRP; g++) {
        int n = base + g;
        float hs = 0.f, hn = 0.f;
        int d = -1;
        if (n < N) {
            int beg = g_rowbeg[n], end = g_rowend[n];
            d = min(end - beg, DMAX);
            int j = beg;
            for (; j + 4 <= end; j += 4) {
                int s0 = __ldg(g_csr + j + 0);
                int s1 = __ldg(g_csr + j + 1);
                int s2 = __ldg(g_csr + j + 2);
                int s3 = __ldg(g_csr + j + 3);
                hs += g_h[(size_t)s0 * FH + lane] + g_h[(size_t)s1 * FH + lane]
                    + g_h[(size_t)s2 * FH + lane] + g_h[(size_t)s3 * FH + lane];
            }
            for (; j < end; j++) {
                int s = __ldg(g_csr + j);
                hs += g_h[(size_t)s * FH + lane];
            }
            hn = g_h[(size_t)n * FH + lane];
        }
        dg[g] = d;
        hh[g * FH + lane] = pack2(hs, hn);
    }
    __syncwarp();

    bool all10 = true;
#pragma unroll
    for (int g = 0; g < GRP; g++) all10 = all10 && (dg[g] == DMAX);

    const u64* W10 = g_Wp2 + DMAX * FH * FO;
#pragma unroll
    for (int half = 0; half < 2; half++) {
        int o = half * 32 + lane;
        u64 acc[GRP];
#pragma unroll
        for (int g = 0; g < GRP; g++)
            acc[g] = pack2((dg[g] >= 0) ? __ldg(b2 + dg[g] * FO + o) : 0.f, 0.f);

        if (all10) {
#pragma unroll 8
            for (int j = 0; j < FH; j++) {
                u64 wv = __ldg(W10 + j * FO + o);
#pragma unroll
                for (int g = 0; g < GRP; g++) fma2(acc[g], hh[g * FH + j], wv);
            }
        } else {
#pragma unroll 8
            for (int j = 0; j < FH; j++) {
                u64 wv = __ldg(W10 + j * FO + o);
#pragma unroll
                for (int g = 0; g < GRP; g++)
                    if (dg[g] == DMAX) fma2(acc[g], hh[g * FH + j], wv);
            }
#pragma unroll
            for (int g = 0; g < GRP; g++) {
                if (dg[g] < 0 || dg[g] == DMAX) continue;
                const u64* Wp = g_Wp2 + dg[g] * FH * FO;
#pragma unroll 8
                for (int j = 0; j < FH; j++)
                    fma2(acc[g], hh[g * FH + j], __ldg(Wp + j * FO + o));
            }
        }
#pragma unroll
        for (int g = 0; g < GRP; g++) {
            int n = base + g;
            if (dg[g] >= 0) {
                float lo, hi; unpack2(acc[g], lo, hi);
                out[(size_t)n * FO + o] = lo + hi;
            }
        }
    }
}

// ============================================================================
extern "C" void kernel_launch(void* const* d_in, const int* in_sizes, int n_in,
                              void* d_out, int out_size) {
    const float* x   = (const float*)d_in[0];
    const int*   ei  = (const int*)d_in[1];     // int32 (JAX x64 disabled)
    const float* W1  = (const float*)d_in[2];
    const float* b1  = (const float*)d_in[3];
    const float* Wr1 = (const float*)d_in[4];
    const float* W2  = (const float*)d_in[5];
    const float* b2  = (const float*)d_in[6];
    const float* Wr2 = (const float*)d_in[7];
    float* out = (float*)d_out;

    int N = in_sizes[0] / FIN;
    int E = in_sizes[1] / 2;
    if (N > NMAX) N = NMAX;
    if (E > EMAX) E = EMAX;

    int nb    = (N + TPB - 1) / TPB;           // covers NW1=45056 too
    int egrid = (E + TPB - 1) / TPB;
    int nwarps = (N + GRP - 1) / GRP;
    int f1grid = (nwarps * 32 + TPB1 - 1) / TPB1;
    int f2grid = (nwarps * 32 + TPB - 1) / TPB;

    k_hist  <<<egrid, TPB>>>(ei, E, N);                // launch 0
    k_alloc <<<nb,    TPB>>>(W1, Wr1, W2, Wr2, N);     // launch 1
    k_place <<<egrid, TPB>>>(ei, E, N);                // launch 2
    k_fused1<<<f1grid, TPB1>>>(x, b1, N);              // launch 3  <- profiled
    k_fused2<<<f2grid, TPB>>>(b2, out, N);             // launch 4
}

// round 13
// speedup vs baseline: 1.3597x; 1.0113x over previous
#include <cuda_runtime.h>

// MFNet two-layer MFConv — project-then-aggregate for the deg==10 majority.
// R12 profile: fused1 is LSU-wavefront bound (duration invariant to occupancy
// and to weight-traffic cuts). Dominant term = 512B x-row gather (4 wf/edge).
// Fix: pre-project ALL nodes once (y10=x@W1[10], r10=x@Wr1[10]); majority
// aggregation then gathers 128B y10 rows (1 wf/edge). Minority (deg<10, ~4%)
// via compacted list + wide gather. fused2: single-pass dual-half accs +
// LDS.128 paired a-operands.
// Replay-safe: g_deg restored by k_place, g_total/g_mcnt by k_fused2.

#define NMAX 100352
#define EMAX 1664000
#define FIN  128
#define FH   32
#define FO   64
#define DMAX 10
#define TPB  256
#define GRP  8
#define NW1  (11 * FIN * FH)   // 45056
#define NW2  (11 * FH * FO)    // 22528

typedef unsigned long long u64;

// scratch (static __device__ — no allocations allowed)
__device__ int g_deg[NMAX];      // INVARIANT zero at entry (restored: k_place)
__device__ int g_total;          // INVARIANT zero at entry (restored: k_fused2)
__device__ int g_mcnt;           // INVARIANT zero at entry (restored: k_fused2)
__device__ int g_mlist[NMAX];
__device__ int g_rowbeg[NMAX];
__device__ int g_rowend[NMAX];
__device__ int g_cursor[NMAX];
__device__ int g_csr[EMAX];
__device__ __align__(16) float g_h[NMAX * FH];      // 12.8 MB
__device__ __align__(16) float g_y10[NMAX * FH];    // x @ W1[10]
__device__ __align__(16) float g_r10[NMAX * FH];    // x @ Wr1[10]
__device__ __align__(16) u64 g_Wp1[NW1];            // (W1,Wr1) interleaved
__device__ __align__(16) u64 g_Wp2[NW2];            // (W2,Wr2) interleaved

__device__ __forceinline__ u64 pack2(float lo, float hi) {
    u64 r; asm("mov.b64 %0, {%1, %2};" : "=l"(r) : "f"(lo), "f"(hi)); return r;
}
__device__ __forceinline__ void unpack2(u64 v, float& lo, float& hi) {
    asm("mov.b64 {%0, %1}, %2;" : "=f"(lo), "=f"(hi) : "l"(v));
}
__device__ __forceinline__ void fma2(u64& d, u64 a, u64 b) {
    asm("fma.rn.f32x2 %0, %1, %2, %0;" : "+l"(d) : "l"(a), "l"(b));
}

// ------------------------------------------- [0] degree histogram (deg==0 in)
__global__ void k_hist(const int* __restrict__ ei, int E, int N) {
    int e = blockIdx.x * blockDim.x + threadIdx.x;
    if (e >= E) return;
    int d = __ldg(ei + E + e);
    if ((unsigned)d < (unsigned)N) atomicAdd(g_deg + d, 1);
}

// ---------------- [1] slice allocation (warp-aggregated atomic) + weight pack
__global__ void k_alloc(const float* __restrict__ W1, const float* __restrict__ Wr1,
                        const float* __restrict__ W2, const float* __restrict__ Wr2,
                        int N) {
    int i = blockIdx.x * blockDim.x + threadIdx.x;
    if (i < NW1) g_Wp1[i] = pack2(__ldg(W1 + i), __ldg(Wr1 + i));
    if (i < NW2) g_Wp2[i] = pack2(__ldg(W2 + i), __ldg(Wr2 + i));

    int lane = threadIdx.x & 31;
    int d = (i < N) ? g_deg[i] : 0;
    int incl = d;
#pragma unroll
    for (int off = 1; off < 32; off <<= 1) {
        int v = __shfl_up_sync(0xffffffffu, incl, off);
        if (lane >= off) incl += v;
    }
    int wtot = __shfl_sync(0xffffffffu, incl, 31);
    int base = 0;
    if (lane == 31) base = atomicAdd(&g_total, wtot);
    base = __shfl_sync(0xffffffffu, base, 31);
    int beg = base + incl - d;
    if (i < N) { g_rowbeg[i] = beg; g_rowend[i] = beg + d; g_cursor[i] = beg; }
}

// ------- [2] CSR placement + minority list; restores g_deg=0 entry invariant
__global__ void k_place(const int* __restrict__ ei, int E, int N) {
    int e = blockIdx.x * blockDim.x + threadIdx.x;
    if (e < N) {
        g_deg[e] = 0;                        // consumed by k_alloc; restore
        if (g_rowend[e] - g_rowbeg[e] < DMAX)
            g_mlist[atomicAdd(&g_mcnt, 1)] = e;   // single counter, aggregated
    }
    if (e >= E) return;
    int s = __ldg(ei + e);
    int d = __ldg(ei + E + e);
    if ((unsigned)s >= (unsigned)N || (unsigned)d >= (unsigned)N) return;
    int pos = atomicAdd(g_cursor + d, 1);
    if (pos < EMAX) g_csr[pos] = s;
}

// --------- [3] per-node bucket-10 projection (PROFILED SLOT), GRP=8/warp
// lane = output channel; a-operand = broadcast LDG.64 pair of x (no smem).
__global__ __launch_bounds__(TPB) void k_proj1(const float* __restrict__ x, int N) {
    int gw = (blockIdx.x * blockDim.x + threadIdx.x) >> 5;
    int lane = threadIdx.x & 31;
    int base = gw * GRP;
    if (base >= N) return;

    const float2* xrow[GRP];
#pragma unroll
    for (int g = 0; g < GRP; g++) {
        int n = base + g;
        xrow[g] = reinterpret_cast<const float2*>(x + (size_t)min(n, N - 1) * FIN);
    }
    u64 acc[GRP];
#pragma unroll
    for (int g = 0; g < GRP; g++) acc[g] = 0ull;

    const u64* W10 = g_Wp1 + DMAX * FIN * FH;
#pragma unroll 4
    for (int f2 = 0; f2 < FIN / 2; f2++) {
        u64 w0 = __ldg(W10 + (2 * f2 + 0) * FH + lane);
        u64 w1 = __ldg(W10 + (2 * f2 + 1) * FH + lane);
#pragma unroll
        for (int g = 0; g < GRP; g++) {
            float2 xa = __ldg(xrow[g] + f2);           // broadcast, L1-hot
            fma2(acc[g], pack2(xa.x, xa.x), w0);
            fma2(acc[g], pack2(xa.y, xa.y), w1);
        }
    }
#pragma unroll
    for (int g = 0; g < GRP; g++) {
        int n = base + g;
        if (n < N) {
            float y, r; unpack2(acc[g], y, r);
            g_y10[(size_t)n * FH + lane] = y;
            g_r10[(size_t)n * FH + lane] = r;
        }
    }
}

// ---------- [4] majority aggregation (deg>=10): gather 128B y10 rows (1 wf/e)
__global__ __launch_bounds__(TPB) void k_agg1(const float* __restrict__ b1, int N) {
    int t = blockIdx.x * blockDim.x + threadIdx.x;
    int n = t >> 5, lane = t & 31;
    if (n >= N) return;
    int beg = g_rowbeg[n], end = g_rowend[n];
    if (end - beg < DMAX) return;            // minority handled by k_minor1
    float hs = 0.f;
    int j = beg;
    for (; j + 4 <= end; j += 4) {
        int s0 = __ldg(g_csr + j + 0);
        int s1 = __ldg(g_csr + j + 1);
        int s2 = __ldg(g_csr + j + 2);
        int s3 = __ldg(g_csr + j + 3);
        hs += __ldg(g_y10 + (size_t)s0 * FH + lane)
            + __ldg(g_y10 + (size_t)s1 * FH + lane)
            + __ldg(g_y10 + (size_t)s2 * FH + lane)
            + __ldg(g_y10 + (size_t)s3 * FH + lane);
    }
    for (; j < end; j++) {
        int s = __ldg(g_csr + j);
        hs += __ldg(g_y10 + (size_t)s * FH + lane);
    }
    hs += __ldg(b1 + DMAX * FH + lane) + g_r10[(size_t)n * FH + lane];
    g_h[(size_t)n * FH + lane] = fmaxf(hs, 0.f);
}

// -------------- [5] minority (deg<10): wide x gather + per-bucket matvec
__global__ __launch_bounds__(TPB) void k_minor1(const float* __restrict__ x,
                                                const float* __restrict__ b1) {
    int gw = (blockIdx.x * blockDim.x + threadIdx.x) >> 5;
    int lane = threadIdx.x & 31;
    if (gw >= g_mcnt) return;
    int n = g_mlist[gw];
    int beg = g_rowbeg[n], end = g_rowend[n];
    int d = min(end - beg, DMAX);

    float a0 = 0.f, a1 = 0.f, a2 = 0.f, a3 = 0.f;
    for (int j = beg; j < end; j++) {
        int s = __ldg(g_csr + j);
        float4 v = *reinterpret_cast<const float4*>(x + (size_t)s * FIN + lane * 4);
        a0 += v.x; a1 += v.y; a2 += v.z; a3 += v.w;
    }
    float4 xr = *reinterpret_cast<const float4*>(x + (size_t)n * FIN + lane * 4);

    const u64* Wp = g_Wp1 + d * FIN * FH;
    u64 acc = pack2(__ldg(b1 + d * FH + lane), 0.f);
#pragma unroll
    for (int q = 0; q < 32; q++) {
        float h0 = __shfl_sync(0xffffffffu, a0, q);
        float h1 = __shfl_sync(0xffffffffu, a1, q);
        float h2 = __shfl_sync(0xffffffffu, a2, q);
        float h3 = __shfl_sync(0xffffffffu, a3, q);
        float x0 = __shfl_sync(0xffffffffu, xr.x, q);
        float x1 = __shfl_sync(0xffffffffu, xr.y, q);
        float x2 = __shfl_sync(0xffffffffu, xr.z, q);
        float x3 = __shfl_sync(0xffffffffu, xr.w, q);
        int f = q * 4;
        fma2(acc, pack2(h0, x0), __ldg(Wp + (f + 0) * FH + lane));
        fma2(acc, pack2(h1, x1), __ldg(Wp + (f + 1) * FH + lane));
        fma2(acc, pack2(h2, x2), __ldg(Wp + (f + 2) * FH + lane));
        fma2(acc, pack2(h3, x3), __ldg(Wp + (f + 3) * FH + lane));
    }
    float lo, hi; unpack2(acc, lo, hi);
    g_h[(size_t)n * FH + lane] = fmaxf(lo + hi, 0.f);
}

// --- [6] layer 2: fused gather + transform (single pass, dual-half accs);
//         restores g_total=0 and g_mcnt=0 entry invariants
__global__ __launch_bounds__(TPB) void k_fused2(const float* __restrict__ b2,
                                                float* __restrict__ out, int N) {
    if (blockIdx.x == 0 && threadIdx.x == 0) { g_total = 0; g_mcnt = 0; }
    __shared__ __align__(16) u64 sh[TPB / 32][GRP * FH];   // 8 warps x 2KB
    int gw = (blockIdx.x * blockDim.x + threadIdx.x) >> 5;
    int lane = threadIdx.x & 31;
    u64* hh = sh[threadIdx.x >> 5];
    int base = gw * GRP;
    if (base >= N) return;

    int dg[GRP];
#pragma unroll
    for (int g = 0; g < GRP; g++) {
        int n = base + g;
        float hs = 0.f, hn = 0.f;
        int d = -1;
        if (n < N) {
            int beg = g_rowbeg[n], end = g_rowend[n];
            d = min(end - beg, DMAX);
            int j = beg;
            for (; j + 4 <= end; j += 4) {
                int s0 = __ldg(g_csr + j + 0);
                int s1 = __ldg(g_csr + j + 1);
                int s2 = __ldg(g_csr + j + 2);
                int s3 = __ldg(g_csr + j + 3);
                hs += g_h[(size_t)s0 * FH + lane] + g_h[(size_t)s1 * FH + lane]
                    + g_h[(size_t)s2 * FH + lane] + g_h[(size_t)s3 * FH + lane];
            }
            for (; j < end; j++) {
                int s = __ldg(g_csr + j);
                hs += g_h[(size_t)s * FH + lane];
            }
            hn = g_h[(size_t)n * FH + lane];
        }
        dg[g] = d;
        hh[g * FH + lane] = pack2(hs, hn);
    }
    __syncwarp();

    bool all10 = true;
#pragma unroll
    for (int g = 0; g < GRP; g++) all10 = all10 && (dg[g] == DMAX);

    u64 accA[GRP], accB[GRP];
#pragma unroll
    for (int g = 0; g < GRP; g++) {
        accA[g] = pack2((dg[g] >= 0) ? __ldg(b2 + dg[g] * FO + lane) : 0.f, 0.f);
        accB[g] = pack2((dg[g] >= 0) ? __ldg(b2 + dg[g] * FO + 32 + lane) : 0.f, 0.f);
    }

    const u64* W10 = g_Wp2 + DMAX * FH * FO;
    if (all10) {
#pragma unroll 4
        for (int j2 = 0; j2 < FH / 2; j2++) {
            u64 w00 = __ldg(W10 + (2 * j2 + 0) * FO + lane);
            u64 w01 = __ldg(W10 + (2 * j2 + 0) * FO + 32 + lane);
            u64 w10 = __ldg(W10 + (2 * j2 + 1) * FO + lane);
            u64 w11 = __ldg(W10 + (2 * j2 + 1) * FO + 32 + lane);
#pragma unroll
            for (int g = 0; g < GRP; g++) {
                ulonglong2 hp = *reinterpret_cast<const ulonglong2*>(hh + g * FH + 2 * j2);
                fma2(accA[g], hp.x, w00);
                fma2(accB[g], hp.x, w01);
                fma2(accA[g], hp.y, w10);
                fma2(accB[g], hp.y, w11);
            }
        }
    } else {
#pragma unroll 4
        for (int j2 = 0; j2 < FH / 2; j2++) {
            u64 w00 = __ldg(W10 + (2 * j2 + 0) * FO + lane);
            u64 w01 = __ldg(W10 + (2 * j2 + 0) * FO + 32 + lane);
            u64 w10 = __ldg(W10 + (2 * j2 + 1) * FO + lane);
            u64 w11 = __ldg(W10 + (2 * j2 + 1) * FO + 32 + lane);
#pragma unroll
            for (int g = 0; g < GRP; g++) {
                if (dg[g] != DMAX) continue;
                ulonglong2 hp = *reinterpret_cast<const ulonglong2*>(hh + g * FH + 2 * j2);
                fma2(accA[g], hp.x, w00);
                fma2(accB[g], hp.x, w01);
                fma2(accA[g], hp.y, w10);
                fma2(accB[g], hp.y, w11);
            }
        }
#pragma unroll
        for (int g = 0; g < GRP; g++) {
            if (dg[g] < 0 || dg[g] == DMAX) continue;
            const u64* Wp = g_Wp2 + dg[g] * FH * FO;
#pragma unroll 8
            for (int j = 0; j < FH; j++) {
                u64 hv = hh[g * FH + j];
                fma2(accA[g], hv, __ldg(Wp + j * FO + lane));
                fma2(accB[g], hv, __ldg(Wp + j * FO + 32 + lane));
            }
        }
    }
#pragma unroll
    for (int g = 0; g < GRP; g++) {
        int n = base + g;
        if (dg[g] >= 0) {
            float lo, hi;
            unpack2(accA[g], lo, hi);
            out[(size_t)n * FO + lane] = lo + hi;
            unpack2(accB[g], lo, hi);
            out[(size_t)n * FO + 32 + lane] = lo + hi;
        }
    }
}

// ============================================================================
extern "C" void kernel_launch(void* const* d_in, const int* in_sizes, int n_in,
                              void* d_out, int out_size) {
    const float* x   = (const float*)d_in[0];
    const int*   ei  = (const int*)d_in[1];     // int32 (JAX x64 disabled)
    const float* W1  = (const float*)d_in[2];
    const float* b1  = (const float*)d_in[3];
    const float* Wr1 = (const float*)d_in[4];
    const float* W2  = (const float*)d_in[5];
    const float* b2  = (const float*)d_in[6];
    const float* Wr2 = (const float*)d_in[7];
    float* out = (float*)d_out;

    int N = in_sizes[0] / FIN;
    int E = in_sizes[1] / 2;
    if (N > NMAX) N = NMAX;
    if (E > EMAX) E = EMAX;

    int nb    = (N + TPB - 1) / TPB;           // covers NW1=45056 too
    int egrid = (E + TPB - 1) / TPB;
    int nwarps = (N + GRP - 1) / GRP;
    int ggrid = (nwarps * 32 + TPB - 1) / TPB;
    int wgrid = (N * 32 + TPB - 1) / TPB;      // warp-per-node grids

    k_hist  <<<egrid, TPB>>>(ei, E, N);                // 0
    k_alloc <<<nb,    TPB>>>(W1, Wr1, W2, Wr2, N);     // 1
    k_place <<<egrid, TPB>>>(ei, E, N);                // 2
    k_proj1 <<<ggrid, TPB>>>(x, N);                    // 3  <- profiled
    k_agg1  <<<wgrid, TPB>>>(b1, N);                   // 4
    k_minor1<<<wgrid, TPB>>>(x, b1);                   // 5
    k_fused2<<<ggrid, TPB>>>(b2, out, N);              // 6
}